// round 2
// baseline (speedup 1.0000x reference)
#include <cuda_runtime.h>
#include <cstdint>

#define EMB 256
#define H1 1024
#define H2 512
#define NENT 700
#define KC 16
#define TA 8
#define TB 8
#define NTH 512
#define NCHUNKS (H1/KC)

// Scratch (allowed: __device__ globals)
__device__ float g_ent[NENT*EMB];
__device__ float g_hA[NENT*H1];
__device__ float g_hB[NENT*H1];

// Pair task tables: (aType, bType) per the 10 outputs, entity type layout is
// contiguous [drug 0:200, prot 200:400, dis 400:550, se 550:700].
__constant__ int c_aType[10]  = {0,0,0,0,1,1,1,3,2,2};
__constant__ int c_bType[10]  = {1,0,2,3,2,1,0,0,1,0};
__constant__ int c_base[4]    = {0,200,400,550};
__constant__ int c_cnt[4]     = {200,200,150,150};
__constant__ int c_outOff[10] = {0,40000,80000,110000,140000,170000,210000,250000,280000,310000};

// ---------------- Kernel 1: ent = E @ W_ent, also emit drug rows -------------
__global__ void k_ent(const float* __restrict__ E, const float* __restrict__ W,
                      float* __restrict__ outDrug)
{
    __shared__ float sE[EMB];
    int row = blockIdx.x, tid = threadIdx.x;
    sE[tid] = E[row*EMB + tid];
    __syncthreads();
    float acc = 0.f;
    #pragma unroll 8
    for (int k = 0; k < EMB; ++k) acc = fmaf(sE[k], W[k*EMB + tid], acc);
    g_ent[row*EMB + tid] = acc;
    if (row < 200) outDrug[row*EMB + tid] = acc;   // drug = ent[0:200]
}

// ------------- Kernel 2: hA = ent@W1a ; hB = ent@W1b + b1 --------------------
__global__ void k_h(const float* __restrict__ W1, const float* __restrict__ b1)
{
    __shared__ float sE[EMB];
    int row = blockIdx.x, which = blockIdx.y, tid = threadIdx.x;
    sE[tid] = g_ent[row*EMB + tid];
    __syncthreads();
    const float* W = W1 + which*EMB*H1;  // W1[:256] or W1[256:]
    float a0=0.f, a1=0.f, a2=0.f, a3=0.f;
    #pragma unroll 4
    for (int k = 0; k < EMB; ++k){
        float e = sE[k];
        const float* w = W + k*H1 + tid;
        a0 = fmaf(e, w[0],   a0);
        a1 = fmaf(e, w[256], a1);
        a2 = fmaf(e, w[512], a2);
        a3 = fmaf(e, w[768], a3);
    }
    if (which){ a0 += b1[tid]; a1 += b1[tid+256]; a2 += b1[tid+512]; a3 += b1[tid+768]; }
    float* dst = which ? g_hB : g_hA;
    dst[row*H1 + tid      ] = a0;
    dst[row*H1 + tid + 256] = a1;
    dst[row*H1 + tid + 512] = a2;
    dst[row*H1 + tid + 768] = a3;
}

// ---------------- Kernel 3: fused pair MLP + softmax -------------------------
__device__ __forceinline__ void cp16(float* smem_dst, const float* gmem_src){
    uint32_t s = (uint32_t)__cvta_generic_to_shared(smem_dst);
    asm volatile("cp.async.ca.shared.global [%0], [%1], 16;" :: "r"(s), "l"(gmem_src));
}

__global__ void __launch_bounds__(NTH, 1)
k_pairs(const float* __restrict__ W2, const float* __restrict__ b2,
        const float* __restrict__ W3, const float* __restrict__ b3,
        float* __restrict__ out)
{
    extern __shared__ float smem[];
    float* sHA = smem;                    // TA*H1
    float* sHB = sHA + TA*H1;             // TB*H1
    float* sW2 = sHB + TB*H1;             // 2*KC*H2 (double buffered)
    float* sW3 = sW2 + 2*KC*H2;           // H2*2
    float* sB2 = sW3 + H2*2;              // H2

    const int task = blockIdx.y;
    const int at = c_aType[task], bt = c_bType[task];
    const int aBase = c_base[at], Na = c_cnt[at];
    const int bBase = c_base[bt], Nb = c_cnt[bt];
    const int tilesA = (Na + TA - 1)/TA, tilesB = (Nb + TB - 1)/TB;
    const int tile = blockIdx.x;
    if (tile >= tilesA*tilesB) return;
    const int i0 = (tile / tilesB) * TA;
    const int j0 = (tile % tilesB) * TB;
    const int tid = threadIdx.x;

    // Stage hA/hB tile rows (clamped; out-of-range pairs predicated at write)
    for (int idx = tid; idx < TA*(H1/4); idx += NTH){
        int r = idx >> 8, k4 = idx & 255;
        int row = aBase + min(i0 + r, Na - 1);
        ((float4*)sHA)[idx] = ((const float4*)(g_hA + row*H1))[k4];
    }
    for (int idx = tid; idx < TB*(H1/4); idx += NTH){
        int r = idx >> 8, k4 = idx & 255;
        int row = bBase + min(j0 + r, Nb - 1);
        ((float4*)sHB)[idx] = ((const float4*)(g_hB + row*H1))[k4];
    }
    for (int k = tid; k < H2*2; k += NTH) sW3[k] = W3[k];
    for (int k = tid; k < H2;   k += NTH) sB2[k] = b2[k];

    // Prefetch W2 chunk 0
    {
        #pragma unroll
        for (int t = 0; t < 4; ++t){
            int idx = tid + t*NTH;
            cp16(sW2 + idx*4, W2 + idx*4);
        }
        asm volatile("cp.async.commit_group;");
    }

    float acc[4][16];
    #pragma unroll
    for (int i = 0; i < 4; ++i)
        #pragma unroll
        for (int j = 0; j < 16; ++j) acc[i][j] = 0.f;

    const int mt = tid >> 5;   // 0..15  -> m in {mt, mt+16, mt+32, mt+48}
    const int nt = tid & 31;   // 0..31  -> n in {q*128 + nt*4 + e}
    const float* pA = sHA + (mt >> 3) * H1;   // a(mm) = (mt>>3) + 2*mm
    const float* pB = sHB + (mt & 7) * H1;    // b constant per thread

    asm volatile("cp.async.wait_group 0;");
    __syncthreads();

    for (int c = 0; c < NCHUNKS; ++c){
        int buf = c & 1;
        if (c + 1 < NCHUNKS){
            const float* src = W2 + (c+1)*KC*H2;
            float* dst = sW2 + (buf^1)*KC*H2;
            #pragma unroll
            for (int t = 0; t < 4; ++t){
                int idx = tid + t*NTH;
                cp16(dst + idx*4, src + idx*4);
            }
            asm volatile("cp.async.commit_group;");
        }
        const float* w2 = sW2 + buf*KC*H2;
        const int kbase = c*KC;
        #pragma unroll 4
        for (int kk = 0; kk < KC; ++kk){
            int k = kbase + kk;
            float hb = pB[k];
            float h[4];
            #pragma unroll
            for (int mm = 0; mm < 4; ++mm)
                h[mm] = fmaxf(pA[2*mm*H1 + k] + hb, 0.f);
            const float* wr = w2 + kk*H2 + nt*4;
            #pragma unroll
            for (int q = 0; q < 4; ++q){
                float4 w = *(const float4*)(wr + q*128);
                #pragma unroll
                for (int mm = 0; mm < 4; ++mm){
                    acc[mm][q*4+0] = fmaf(h[mm], w.x, acc[mm][q*4+0]);
                    acc[mm][q*4+1] = fmaf(h[mm], w.y, acc[mm][q*4+1]);
                    acc[mm][q*4+2] = fmaf(h[mm], w.z, acc[mm][q*4+2]);
                    acc[mm][q*4+3] = fmaf(h[mm], w.w, acc[mm][q*4+3]);
                }
            }
        }
        asm volatile("cp.async.wait_group 0;");
        __syncthreads();
    }

    // Epilogue: +b2, relu, layer3 (512->2), softmax, write
    const float b30 = b3[0], b31 = b3[1];
    const int outBase = c_outOff[task];
    #pragma unroll
    for (int mm = 0; mm < 4; ++mm){
        float p0 = 0.f, p1 = 0.f;
        #pragma unroll
        for (int q = 0; q < 4; ++q){
            #pragma unroll
            for (int e = 0; e < 4; ++e){
                int n = q*128 + nt*4 + e;
                float v = fmaxf(acc[mm][q*4+e] + sB2[n], 0.f);
                p0 = fmaf(v, sW3[2*n  ], p0);
                p1 = fmaf(v, sW3[2*n+1], p1);
            }
        }
        #pragma unroll
        for (int off = 16; off > 0; off >>= 1){
            p0 += __shfl_down_sync(0xffffffffu, p0, off);
            p1 += __shfl_down_sync(0xffffffffu, p1, off);
        }
        if (nt == 0){
            int m = mt + 16*mm;
            int i = i0 + (m >> 3), j = j0 + (m & 7);
            if (i < Na && j < Nb){
                float l0 = p0 + b30, l1 = p1 + b31;
                float mx = fmaxf(l0, l1);
                float e0 = expf(l0 - mx), e1 = expf(l1 - mx);
                float inv = 1.f / (e0 + e1);
                int idx = (outBase + i*Nb + j) * 2;
                out[idx]   = e0 * inv;
                out[idx+1] = e1 * inv;
            }
        }
    }
}

// -----------------------------------------------------------------------------
extern "C" void kernel_launch(void* const* d_in, const int* in_sizes, int n_in,
                              void* d_out, int out_size)
{
    // metadata order: 0 type_mask, 1 entity_embedding, 2 relation_embedding,
    // 3 W_ent, 4 W_rel, 5 W1, 6 b1, 7 W2, 8 b2, 9 W3, 10 b3
    const float* E    = (const float*)d_in[1];
    const float* Went = (const float*)d_in[3];
    const float* W1   = (const float*)d_in[5];
    const float* b1   = (const float*)d_in[6];
    const float* W2   = (const float*)d_in[7];
    const float* b2   = (const float*)d_in[8];
    const float* W3   = (const float*)d_in[9];
    const float* b3   = (const float*)d_in[10];
    float* out = (float*)d_out;

    k_ent<<<700, 256>>>(E, Went, out + 680000);
    k_h<<<dim3(700, 2), 256>>>(W1, b1);

    int smemBytes = (TA*H1 + TB*H1 + 2*KC*H2 + H2*2 + H2) * (int)sizeof(float);
    cudaFuncSetAttribute(k_pairs, cudaFuncAttributeMaxDynamicSharedMemorySize, smemBytes);
    k_pairs<<<dim3(625, 10), NTH, smemBytes>>>(W2, b2, W3, b3, out);
}

// round 4
// speedup vs baseline: 3.9806x; 3.9806x over previous
#include <cuda_runtime.h>
#include <cuda_bf16.h>
#include <cstdint>

#define EMB 256
#define H1 1024
#define H2 512
#define NENT 700

// ---------------- scratch (__device__ globals; no allocation) ----------------
__device__ float g_ent[NENT*EMB];
__device__ float g_hA[NENT*H1];
__device__ float g_hB[NENT*H1];
__device__ __nv_bfloat16 g_W2t[H2*H1];   // [n][k]  (W2 transposed, bf16)

// task tables: entity layout [drug 0:200, prot 200:400, dis 400:550, se 550:700]
__constant__ int c_aType[10]  = {0,0,0,0,1,1,1,3,2,2};
__constant__ int c_bType[10]  = {1,0,2,3,2,1,0,0,1,0};
__constant__ int c_base[4]    = {0,200,400,550};
__constant__ int c_cnt[4]     = {200,200,150,150};
__constant__ int c_outOff[10] = {0,40000,80000,110000,140000,170000,210000,250000,280000,310000};

// ---------------- Kernel 1: ent = E @ W_ent, emit drug rows ------------------
__global__ void k_ent(const float* __restrict__ E, const float* __restrict__ W,
                      float* __restrict__ outDrug)
{
    __shared__ float sE[EMB];
    int row = blockIdx.x, tid = threadIdx.x;
    sE[tid] = E[row*EMB + tid];
    __syncthreads();
    float acc = 0.f;
    #pragma unroll 8
    for (int k = 0; k < EMB; ++k) acc = fmaf(sE[k], W[k*EMB + tid], acc);
    g_ent[row*EMB + tid] = acc;
    if (row < 200) outDrug[row*EMB + tid] = acc;
}

// ------------- Kernel 2: hA = ent@W1a ; hB = ent@W1b + b1 --------------------
__global__ void k_h(const float* __restrict__ W1, const float* __restrict__ b1)
{
    __shared__ float sE[EMB];
    int row = blockIdx.x, which = blockIdx.y, tid = threadIdx.x;
    sE[tid] = g_ent[row*EMB + tid];
    __syncthreads();
    const float* W = W1 + which*EMB*H1;
    float a0=0.f, a1=0.f, a2=0.f, a3=0.f;
    #pragma unroll 4
    for (int k = 0; k < EMB; ++k){
        float e = sE[k];
        const float* w = W + k*H1 + tid;
        a0 = fmaf(e, w[0],   a0);
        a1 = fmaf(e, w[256], a1);
        a2 = fmaf(e, w[512], a2);
        a3 = fmaf(e, w[768], a3);
    }
    if (which){ a0 += b1[tid]; a1 += b1[tid+256]; a2 += b1[tid+512]; a3 += b1[tid+768]; }
    float* dst = which ? g_hB : g_hA;
    dst[row*H1 + tid      ] = a0;
    dst[row*H1 + tid + 256] = a1;
    dst[row*H1 + tid + 512] = a2;
    dst[row*H1 + tid + 768] = a3;
}

// ------------- Kernel 2b: W2t[n][k] = bf16(W2[k][n]) -------------------------
__global__ void k_prep(const float* __restrict__ W2)
{
    __shared__ float tile[32][33];
    int k0 = blockIdx.x*32, n0 = blockIdx.y*32;
    int tx = threadIdx.x, ty = threadIdx.y;
    tile[ty][tx] = W2[(k0+ty)*H2 + n0 + tx];
    __syncthreads();
    g_W2t[(uint32_t)(n0+ty)*H1 + k0 + tx] = __float2bfloat16(tile[tx][ty]);
}

// ---------------- mma helpers ------------------------------------------------
__device__ __forceinline__ void cp16(void* smem_dst, const void* gmem_src){
    uint32_t s = (uint32_t)__cvta_generic_to_shared(smem_dst);
    asm volatile("cp.async.ca.shared.global [%0], [%1], 16;" :: "r"(s), "l"(gmem_src));
}
__device__ __forceinline__ void ldsm4(uint32_t& r0, uint32_t& r1, uint32_t& r2,
                                      uint32_t& r3, uint32_t addr){
    asm volatile("ldmatrix.sync.aligned.m8n8.x4.shared.b16 {%0,%1,%2,%3}, [%4];"
                 : "=r"(r0), "=r"(r1), "=r"(r2), "=r"(r3) : "r"(addr));
}
__device__ __forceinline__ void mma16816(float* c, const uint32_t* a,
                                         uint32_t b0, uint32_t b1){
    asm volatile(
        "mma.sync.aligned.m16n8k16.row.col.f32.bf16.bf16.f32 "
        "{%0,%1,%2,%3},{%4,%5,%6,%7},{%8,%9},{%0,%1,%2,%3};"
        : "+f"(c[0]), "+f"(c[1]), "+f"(c[2]), "+f"(c[3])
        : "r"(a[0]), "r"(a[1]), "r"(a[2]), "r"(a[3]), "r"(b0), "r"(b1));
}

// ---------------- Kernel 3: fused pair MLP + softmax (mma.sync) --------------
// CTA: M=128 pairs (16a x 8b), N=512 in 2 halves of 256, K=1024 in 16 chunks of 64.
// SMEM layout (bytes):
#define SA_PITCH 144
#define SB_PITCH 144
#define SR_PITCH 272            // 68 floats
#define SA_BUF   (128*SA_PITCH) // 18432
#define SB_BUF   (256*SB_PITCH) // 36864
#define SR_BUF   (24*SR_PITCH)  // 6528
#define OFF_SA   0
#define OFF_SB   (2*SA_BUF)                 // 36864
#define OFF_SR   (OFF_SB + 2*SB_BUF)        // 110592
#define OFF_P0   (OFF_SR + 2*SR_BUF)        // 123648
#define OFF_P1   (OFF_P0 + 512)             // 124160
#define OFF_B2   (OFF_P1 + 512)             // 124672
#define OFF_W3   (OFF_B2 + 2048)            // 126720
#define SMEM_REQ (OFF_W3 + 4096)            // 130816

__global__ void __launch_bounds__(512, 1)
k_pairs(const float* __restrict__ b2, const float* __restrict__ W3,
        const float* __restrict__ b3, float* __restrict__ out)
{
    extern __shared__ __align__(16) char sm[];
    const uint32_t smu = (uint32_t)__cvta_generic_to_shared(sm);

    const int task = blockIdx.y;
    const int at = c_aType[task], bt = c_bType[task];
    const int aBase = c_base[at], Na = c_cnt[at];
    const int bBase = c_base[bt], Nb = c_cnt[bt];
    const int tilesA = (Na + 15) >> 4, tilesB = (Nb + 7) >> 3;
    if ((int)blockIdx.x >= tilesA*tilesB) return;
    const int i0 = ((int)blockIdx.x / tilesB) * 16;
    const int j0 = ((int)blockIdx.x % tilesB) * 8;
    const int tid = threadIdx.x;
    const int l   = tid & 31, wid = tid >> 5;
    const int wm  = wid & 3,  wn  = wid >> 2;

    float*  sB2 = (float*)(sm + OFF_B2);
    float2* sW3 = (float2*)(sm + OFF_W3);
    float*  p0s = (float*)(sm + OFF_P0);
    float*  p1s = (float*)(sm + OFF_P1);

    if (tid < 512){
        sB2[tid] = b2[tid];
        sW3[tid] = make_float2(W3[2*tid], W3[2*tid+1]);
    }
    if (tid < 128){ p0s[tid] = 0.f; p1s[tid] = 0.f; }
    __syncthreads();

    // lane-constant ldmatrix addresses
    const uint32_t aLane = smu + OFF_SA
        + (uint32_t)(wm*32 + (l&7) + ((l>>3)&1)*8) * SA_PITCH + (uint32_t)((l>>4)*8)*2;
    const uint32_t bLane = smu + OFF_SB
        + (uint32_t)(wn*64 + (l&7) + (l>>4)*8) * SB_PITCH + (uint32_t)(((l>>3)&1)*8)*2;

    // synth mapping: 4 threads per A row, 16 cols each
    const int sm_m  = tid >> 2;
    const int sm_sg = tid & 3;

    float acc[2][8][4];

    for (int nh = 0; nh < 2; ++nh){
        #pragma unroll
        for (int mt = 0; mt < 2; ++mt)
            #pragma unroll
            for (int nt = 0; nt < 8; ++nt)
                #pragma unroll
                for (int r = 0; r < 4; ++r) acc[mt][nt][r] = 0.f;

        // chunk issuer (B chunk + distinct-row staging)
        auto issue = [&](int c, int buf){
            #pragma unroll
            for (int i = 0; i < 4; ++i){
                int idx = tid + i*512;
                int row = idx >> 3, seg = idx & 7;
                cp16(sm + OFF_SB + buf*SB_BUF + row*SB_PITCH + seg*16,
                     g_W2t + (uint32_t)(nh*256 + row)*H1 + c*64 + seg*8);
            }
            if (tid < 384){
                int row = tid >> 4, seg = tid & 15;
                const float* src;
                if (row < 16){
                    int r = aBase + min(i0 + row, Na - 1);
                    src = g_hA + (uint32_t)r*H1;
                } else {
                    int r = bBase + min(j0 + row - 16, Nb - 1);
                    src = g_hB + (uint32_t)r*H1;
                }
                cp16(sm + OFF_SR + buf*SR_BUF + row*SR_PITCH + seg*16,
                     src + c*64 + seg*4);
            }
            asm volatile("cp.async.commit_group;");
        };

        issue(0, 0);

        for (int c = 0; c < 16; ++c){
            const int buf = c & 1;
            asm volatile("cp.async.wait_group 0;" ::: "memory");
            __syncthreads();

            // synthesize A chunk: relu(hA_i + hB_j) -> bf16, 128 x 64
            {
                const float* rbuf = (const float*)(sm + OFF_SR + buf*SR_BUF);
                const float* ra = rbuf + (sm_m >> 3) * 68;
                const float* rb = rbuf + (16 + (sm_m & 7)) * 68;
                char* dst = sm + OFF_SA + buf*SA_BUF + sm_m*SA_PITCH + sm_sg*32;
                #pragma unroll
                for (int h = 0; h < 2; ++h){
                    uint32_t w[4];
                    #pragma unroll
                    for (int q = 0; q < 4; ++q){
                        int cc = sm_sg*16 + h*8 + q*2;
                        float v0 = fmaxf(ra[cc]   + rb[cc],   0.f);
                        float v1 = fmaxf(ra[cc+1] + rb[cc+1], 0.f);
                        __nv_bfloat162 bb = __floats2bfloat162_rn(v0, v1);
                        w[q] = *(uint32_t*)&bb;
                    }
                    *(uint4*)(dst + h*16) = make_uint4(w[0], w[1], w[2], w[3]);
                }
            }
            __syncthreads();

            if (c + 1 < 16) issue(c + 1, buf ^ 1);

            // MMA over the chunk
            {
                const uint32_t aAdr = aLane + buf*SA_BUF;
                const uint32_t bAdr = bLane + buf*SB_BUF;
                #pragma unroll
                for (int kt = 0; kt < 4; ++kt){
                    uint32_t a0[4], a1[4];
                    ldsm4(a0[0], a0[1], a0[2], a0[3], aAdr + kt*32);
                    ldsm4(a1[0], a1[1], a1[2], a1[3], aAdr + kt*32 + 16*SA_PITCH);
                    #pragma unroll
                    for (int np = 0; np < 4; ++np){
                        uint32_t b0, b1v, b2v, b3v;
                        ldsm4(b0, b1v, b2v, b3v, bAdr + np*16*SB_PITCH + kt*32);
                        mma16816(acc[0][np*2],   a0, b0,  b1v);
                        mma16816(acc[0][np*2+1], a0, b2v, b3v);
                        mma16816(acc[1][np*2],   a1, b0,  b1v);
                        mma16816(acc[1][np*2+1], a1, b2v, b3v);
                    }
                }
            }
        }

        // fold this N-half into (p0,p1): relu(acc+b2) dot W3
        {
            const int quad = l >> 2, tq = l & 3;
            float pa0[2][2] = {{0.f,0.f},{0.f,0.f}};
            float pa1[2][2] = {{0.f,0.f},{0.f,0.f}};
            #pragma unroll
            for (int mt = 0; mt < 2; ++mt)
                #pragma unroll
                for (int nt = 0; nt < 8; ++nt)
                    #pragma unroll
                    for (int r = 0; r < 4; ++r){
                        int ng = nh*256 + wn*64 + nt*8 + tq*2 + (r & 1);
                        float v = fmaxf(acc[mt][nt][r] + sB2[ng], 0.f);
                        float2 w = sW3[ng];
                        pa0[mt][r>>1] = fmaf(v, w.x, pa0[mt][r>>1]);
                        pa1[mt][r>>1] = fmaf(v, w.y, pa1[mt][r>>1]);
                    }
            #pragma unroll
            for (int mt = 0; mt < 2; ++mt)
                #pragma unroll
                for (int rh = 0; rh < 2; ++rh){
                    float q0 = pa0[mt][rh], q1 = pa1[mt][rh];
                    q0 += __shfl_xor_sync(0xffffffffu, q0, 1);
                    q0 += __shfl_xor_sync(0xffffffffu, q0, 2);
                    q1 += __shfl_xor_sync(0xffffffffu, q1, 1);
                    q1 += __shfl_xor_sync(0xffffffffu, q1, 2);
                    if (tq == 0){
                        int m = wm*32 + mt*16 + quad + rh*8;
                        atomicAdd(&p0s[m], q0);
                        atomicAdd(&p1s[m], q1);
                    }
                }
        }
        __syncthreads();
    }

    // softmax + write
    if (tid < 128){
        int ia = i0 + (tid >> 3), jb = j0 + (tid & 7);
        if (ia < Na && jb < Nb){
            float l0 = p0s[tid] + b3[0], l1 = p1s[tid] + b3[1];
            float mx = fmaxf(l0, l1);
            float e0 = expf(l0 - mx), e1 = expf(l1 - mx);
            float inv = 1.f / (e0 + e1);
            int idx = (c_outOff[task] + ia*Nb + jb) * 2;
            out[idx]   = e0 * inv;
            out[idx+1] = e1 * inv;
        }
    }
}

// -----------------------------------------------------------------------------
extern "C" void kernel_launch(void* const* d_in, const int* in_sizes, int n_in,
                              void* d_out, int out_size)
{
    // 0 type_mask, 1 entity_embedding, 2 relation_embedding, 3 W_ent, 4 W_rel,
    // 5 W1, 6 b1, 7 W2, 8 b2, 9 W3, 10 b3
    const float* E    = (const float*)d_in[1];
    const float* Went = (const float*)d_in[3];
    const float* W1   = (const float*)d_in[5];
    const float* b1   = (const float*)d_in[6];
    const float* W2   = (const float*)d_in[7];
    const float* b2   = (const float*)d_in[8];
    const float* W3   = (const float*)d_in[9];
    const float* b3   = (const float*)d_in[10];
    float* out = (float*)d_out;

    k_ent<<<700, 256>>>(E, Went, out + 680000);
    k_h<<<dim3(700, 2), 256>>>(W1, b1);
    k_prep<<<dim3(32, 16), dim3(32, 32)>>>(W2);

    cudaFuncSetAttribute(k_pairs, cudaFuncAttributeMaxDynamicSharedMemorySize, SMEM_REQ);
    k_pairs<<<dim3(325, 10), 512, SMEM_REQ>>>(b2, W3, b3, out);
}

// round 7
// speedup vs baseline: 6.5442x; 1.6440x over previous
#include <cuda_runtime.h>
#include <cuda_bf16.h>
#include <cstdint>

#define EMB 256
#define H1 1024
#define H2 512
#define NENT 700

// ---------------- scratch (__device__ globals; no allocation) ----------------
__device__ float g_ent[NENT*EMB];
__device__ float g_hA[NENT*H1];
__device__ float g_hB[NENT*H1];
__device__ __nv_bfloat16 g_W2t[H2*H1];   // [n][k]  (W2 transposed, bf16)

// task tables: entity layout [drug 0:200, prot 200:400, dis 400:550, se 550:700]
__constant__ int c_aType[10]  = {0,0,0,0,1,1,1,3,2,2};
__constant__ int c_bType[10]  = {1,0,2,3,2,1,0,0,1,0};
__constant__ int c_base[4]    = {0,200,400,550};
__constant__ int c_cnt[4]     = {200,200,150,150};
__constant__ int c_outOff[10] = {0,40000,80000,110000,140000,170000,210000,250000,280000,310000};

// ---------------- Kernel 1: ent = E @ W_ent, emit drug rows ------------------
__global__ void k_ent(const float* __restrict__ E, const float* __restrict__ W,
                      float* __restrict__ outDrug)
{
    __shared__ float sE[EMB];
    int row = blockIdx.x, tid = threadIdx.x;
    sE[tid] = E[row*EMB + tid];
    __syncthreads();
    float acc = 0.f;
    #pragma unroll 8
    for (int k = 0; k < EMB; ++k) acc = fmaf(sE[k], W[k*EMB + tid], acc);
    g_ent[row*EMB + tid] = acc;
    if (row < 200) outDrug[row*EMB + tid] = acc;
}

// ------------- Kernel 2: hA = ent@W1a ; hB = ent@W1b + b1 --------------------
__global__ void k_h(const float* __restrict__ W1, const float* __restrict__ b1)
{
    __shared__ float sE[EMB];
    int row = blockIdx.x, which = blockIdx.y, tid = threadIdx.x;
    sE[tid] = g_ent[row*EMB + tid];
    __syncthreads();
    const float* W = W1 + which*EMB*H1;
    float a0=0.f, a1=0.f, a2=0.f, a3=0.f;
    #pragma unroll 4
    for (int k = 0; k < EMB; ++k){
        float e = sE[k];
        const float* w = W + k*H1 + tid;
        a0 = fmaf(e, w[0],   a0);
        a1 = fmaf(e, w[256], a1);
        a2 = fmaf(e, w[512], a2);
        a3 = fmaf(e, w[768], a3);
    }
    if (which){ a0 += b1[tid]; a1 += b1[tid+256]; a2 += b1[tid+512]; a3 += b1[tid+768]; }
    float* dst = which ? g_hB : g_hA;
    dst[row*H1 + tid      ] = a0;
    dst[row*H1 + tid + 256] = a1;
    dst[row*H1 + tid + 512] = a2;
    dst[row*H1 + tid + 768] = a3;
}

// ------------- Kernel 2b: W2t[n][k] = bf16(W2[k][n]) -------------------------
__global__ void k_prep(const float* __restrict__ W2)
{
    __shared__ float tile[32][33];
    int k0 = blockIdx.x*32, n0 = blockIdx.y*32;
    int tx = threadIdx.x, ty = threadIdx.y;
    tile[ty][tx] = W2[(k0+ty)*H2 + n0 + tx];
    __syncthreads();
    g_W2t[(uint32_t)(n0+ty)*H1 + k0 + tx] = __float2bfloat16(tile[tx][ty]);
}

// ---------------- mma helpers ------------------------------------------------
__device__ __forceinline__ void cp16cg(void* smem_dst, const void* gmem_src){
    uint32_t s = (uint32_t)__cvta_generic_to_shared(smem_dst);
    asm volatile("cp.async.cg.shared.global [%0], [%1], 16;" :: "r"(s), "l"(gmem_src));
}
__device__ __forceinline__ void ldsm4(uint32_t& r0, uint32_t& r1, uint32_t& r2,
                                      uint32_t& r3, uint32_t addr){
    asm volatile("ldmatrix.sync.aligned.m8n8.x4.shared.b16 {%0,%1,%2,%3}, [%4];"
                 : "=r"(r0), "=r"(r1), "=r"(r2), "=r"(r3) : "r"(addr));
}
__device__ __forceinline__ void mma16816(float* c, const uint32_t* a,
                                         uint32_t b0, uint32_t b1){
    asm volatile(
        "mma.sync.aligned.m16n8k16.row.col.f32.bf16.bf16.f32 "
        "{%0,%1,%2,%3},{%4,%5,%6,%7},{%8,%9},{%0,%1,%2,%3};"
        : "+f"(c[0]), "+f"(c[1]), "+f"(c[2]), "+f"(c[3])
        : "r"(a[0]), "r"(a[1]), "r"(a[2]), "r"(a[3]), "r"(b0), "r"(b1));
}

// ---------------- Kernel 3: fused pair MLP + softmax (mma.sync) --------------
// CTA: M=128 pairs (16a x 8b), N=512 in 2 halves of 256, K=1024 in 16 chunks of 64.
// Pipeline: A double-buffer, B/SR ring-4, ONE syncthreads per chunk.
#define SA_PITCH 144
#define SB_PITCH 144
#define SA_BUF   (128*SA_PITCH)   // 18432
#define SB_BUF   (256*SB_PITCH)   // 36864
#define SR_BUF   (24*272)         // 6528 (24 rows x 68 floats)
#define OFF_SA   0                          // 2 bufs  -> 36864
#define OFF_SB   36864                      // 4 bufs  -> 184320
#define OFF_SR   184320                     // 4 bufs  -> 210432
#define OFF_P0   210432
#define OFF_P1   210944
#define OFF_B2   211456
#define OFF_W3   213504
#define SMEM_REQ 217600

__global__ void __launch_bounds__(512, 1)
k_pairs(const float* __restrict__ b2, const float* __restrict__ W3,
        const float* __restrict__ b3, float* __restrict__ out)
{
    extern __shared__ __align__(16) char sm[];
    const uint32_t smu = (uint32_t)__cvta_generic_to_shared(sm);

    const int task = blockIdx.y;
    const int at = c_aType[task], bt = c_bType[task];
    const int aBase = c_base[at], Na = c_cnt[at];
    const int bBase = c_base[bt], Nb = c_cnt[bt];
    const int tilesA = (Na + 15) >> 4, tilesB = (Nb + 7) >> 3;
    if ((int)blockIdx.x >= tilesA*tilesB) return;
    const int i0 = ((int)blockIdx.x / tilesB) * 16;
    const int j0 = ((int)blockIdx.x % tilesB) * 8;
    const int tid = threadIdx.x;
    const int l   = tid & 31, wid = tid >> 5;
    const int wm  = wid & 3,  wn  = wid >> 2;

    float*  sB2 = (float*)(sm + OFF_B2);
    float2* sW3 = (float2*)(sm + OFF_W3);
    float*  p0s = (float*)(sm + OFF_P0);
    float*  p1s = (float*)(sm + OFF_P1);

    sB2[tid] = b2[tid];
    sW3[tid] = make_float2(W3[2*tid], W3[2*tid+1]);
    if (tid < 128){ p0s[tid] = 0.f; p1s[tid] = 0.f; }
    __syncthreads();

    // lane-constant ldmatrix addresses
    const uint32_t aLane = smu + OFF_SA
        + (uint32_t)(wm*32 + (l&7) + ((l>>3)&1)*8) * SA_PITCH + (uint32_t)((l>>4)*8)*2;
    const uint32_t bLane = smu + OFF_SB
        + (uint32_t)(wn*64 + (l&7) + (l>>4)*8) * SB_PITCH + (uint32_t)(((l>>3)&1)*8)*2;

    // synth mapping: 4 threads per A row, 16 cols each (float4-aligned)
    const int sm_m  = tid >> 2;
    const int sm_sg = tid & 3;
    const int sr_rowA = sm_m >> 3;          // 0..15
    const int sr_rowB = 16 + (sm_m & 7);    // 16..23

    float acc[2][8][4];

    for (int nh = 0; nh < 2; ++nh){
        #pragma unroll
        for (int mt = 0; mt < 2; ++mt)
            #pragma unroll
            for (int nt = 0; nt < 8; ++nt)
                #pragma unroll
                for (int r = 0; r < 4; ++r) acc[mt][nt][r] = 0.f;

        // ---- cp.async issuer: B chunk (ring) + 24 distinct rows (ring) ----
        auto issue = [&](int c, int ring){
            #pragma unroll
            for (int i = 0; i < 4; ++i){
                int idx = tid + i*512;
                int row = idx >> 3, seg = idx & 7;
                cp16cg(sm + OFF_SB + ring*SB_BUF + row*SB_PITCH + seg*16,
                       g_W2t + (uint32_t)(nh*256 + row)*H1 + c*64 + seg*8);
            }
            if (tid < 384){
                int row = tid >> 4, seg = tid & 15;
                const float* src;
                if (row < 16){
                    int r = aBase + min(i0 + row, Na - 1);
                    src = g_hA + (uint32_t)r*H1;
                } else {
                    int r = bBase + min(j0 + row - 16, Nb - 1);
                    src = g_hB + (uint32_t)r*H1;
                }
                cp16cg(sm + OFF_SR + ring*SR_BUF + row*272 + seg*16,
                       src + c*64 + seg*4);
            }
            asm volatile("cp.async.commit_group;");
        };

        // ---- mma over one staged chunk (A parity, B ring) ----
        auto domma = [&](int cc){
            const uint32_t aAdr = aLane + (cc & 1)*SA_BUF;
            const uint32_t bAdr = bLane + (cc & 3)*SB_BUF;
            #pragma unroll
            for (int kt = 0; kt < 4; ++kt){
                uint32_t a0[4], a1[4];
                ldsm4(a0[0], a0[1], a0[2], a0[3], aAdr + kt*32);
                ldsm4(a1[0], a1[1], a1[2], a1[3], aAdr + kt*32 + 16*SA_PITCH);
                #pragma unroll
                for (int np = 0; np < 4; ++np){
                    uint32_t b0, b1v, b2v, b3v;
                    ldsm4(b0, b1v, b2v, b3v, bAdr + np*16*SB_PITCH + kt*32);
                    mma16816(acc[0][np*2],   a0, b0,  b1v);
                    mma16816(acc[0][np*2+1], a0, b2v, b3v);
                    mma16816(acc[1][np*2],   a1, b0,  b1v);
                    mma16816(acc[1][np*2+1], a1, b2v, b3v);
                }
            }
        };

        issue(0, 0);
        issue(1, 1);

        for (int c = 0; c < 16; ++c){
            if (c == 15) asm volatile("cp.async.wait_group 0;" ::: "memory");
            else         asm volatile("cp.async.wait_group 1;" ::: "memory");
            __syncthreads();

            // synth chunk c: relu(hA+hB) -> bf16 into A[c&1], reading SR[c&3]
            {
                const float* rbuf = (const float*)(sm + OFF_SR + (c & 3)*SR_BUF);
                const float4* ra = (const float4*)(rbuf + sr_rowA*68 + sm_sg*16);
                const float4* rb = (const float4*)(rbuf + sr_rowB*68 + sm_sg*16);
                char* dst = sm + OFF_SA + (c & 1)*SA_BUF + sm_m*SA_PITCH + sm_sg*32;
                uint32_t w[8];
                #pragma unroll
                for (int q = 0; q < 4; ++q){
                    float4 x = ra[q], y = rb[q];
                    __nv_bfloat162 v0 = __floats2bfloat162_rn(fmaxf(x.x+y.x,0.f), fmaxf(x.y+y.y,0.f));
                    __nv_bfloat162 v1 = __floats2bfloat162_rn(fmaxf(x.z+y.z,0.f), fmaxf(x.w+y.w,0.f));
                    w[2*q]   = *(uint32_t*)&v0;
                    w[2*q+1] = *(uint32_t*)&v1;
                }
                *(uint4*)(dst)      = make_uint4(w[0], w[1], w[2], w[3]);
                *(uint4*)(dst + 16) = make_uint4(w[4], w[5], w[6], w[7]);
            }

            if (c > 0) domma(c - 1);
            if (c + 2 < 16) issue(c + 2, (c + 2) & 3);
        }
        __syncthreads();   // synth(15) visible
        domma(15);

        // fold this N-half into (p0,p1): relu(acc+b2) dot W3
        {
            const int quad = l >> 2, tq = l & 3;
            float pa0[2][2] = {{0.f,0.f},{0.f,0.f}};
            float pa1[2][2] = {{0.f,0.f},{0.f,0.f}};
            #pragma unroll
            for (int mt = 0; mt < 2; ++mt)
                #pragma unroll
                for (int nt = 0; nt < 8; ++nt)
                    #pragma unroll
                    for (int r = 0; r < 4; ++r){
                        int ng = nh*256 + wn*64 + nt*8 + tq*2 + (r & 1);
                        float v = fmaxf(acc[mt][nt][r] + sB2[ng], 0.f);
                        float2 w = sW3[ng];
                        pa0[mt][r>>1] = fmaf(v, w.x, pa0[mt][r>>1]);
                        pa1[mt][r>>1] = fmaf(v, w.y, pa1[mt][r>>1]);
                    }
            #pragma unroll
            for (int mt = 0; mt < 2; ++mt)
                #pragma unroll
                for (int rh = 0; rh < 2; ++rh){
                    float q0 = pa0[mt][rh], q1 = pa1[mt][rh];
                    q0 += __shfl_xor_sync(0xffffffffu, q0, 1);
                    q0 += __shfl_xor_sync(0xffffffffu, q0, 2);
                    q1 += __shfl_xor_sync(0xffffffffu, q1, 1);
                    q1 += __shfl_xor_sync(0xffffffffu, q1, 2);
                    if (tq == 0){
                        int m = wm*32 + mt*16 + quad + rh*8;
                        atomicAdd(&p0s[m], q0);
                        atomicAdd(&p1s[m], q1);
                    }
                }
        }
        __syncthreads();
    }

    // softmax + write
    if (tid < 128){
        int ia = i0 + (tid >> 3), jb = j0 + (tid & 7);
        if (ia < Na && jb < Nb){
            float l0 = p0s[tid] + b3[0], l1 = p1s[tid] + b3[1];
            float mx = fmaxf(l0, l1);
            float e0 = expf(l0 - mx), e1 = expf(l1 - mx);
            float inv = 1.f / (e0 + e1);
            int idx = (c_outOff[task] + ia*Nb + jb) * 2;
            out[idx]   = e0 * inv;
            out[idx+1] = e1 * inv;
        }
    }
}

// -----------------------------------------------------------------------------
extern "C" void kernel_launch(void* const* d_in, const int* in_sizes, int n_in,
                              void* d_out, int out_size)
{
    // 0 type_mask, 1 entity_embedding, 2 relation_embedding, 3 W_ent, 4 W_rel,
    // 5 W1, 6 b1, 7 W2, 8 b2, 9 W3, 10 b3
    const float* E    = (const float*)d_in[1];
    const float* Went = (const float*)d_in[3];
    const float* W1   = (const float*)d_in[5];
    const float* b1   = (const float*)d_in[6];
    const float* W2   = (const float*)d_in[7];
    const float* b2   = (const float*)d_in[8];
    const float* W3   = (const float*)d_in[9];
    const float* b3   = (const float*)d_in[10];
    float* out = (float*)d_out;

    k_ent<<<700, 256>>>(E, Went, out + 680000);
    k_h<<<dim3(700, 2), 256>>>(W1, b1);
    k_prep<<<dim3(32, 16), dim3(32, 32)>>>(W2);

    cudaFuncSetAttribute(k_pairs, cudaFuncAttributeMaxDynamicSharedMemorySize, SMEM_REQ);
    k_pairs<<<dim3(325, 10), 512, SMEM_REQ>>>(b2, W3, b3, out);
}